// round 6
// baseline (speedup 1.0000x reference)
#include <cuda_runtime.h>
#include <cuda_bf16.h>
#include <cstdint>

constexpr int NB=4, NG=1024, NC=1024, NQ=256, FF=512, HH=8, DD=64;
constexpr size_t SZ_GF=(size_t)NB*NG*FF, SZ_QF=(size_t)NB*NQ*FF;
constexpr size_t O_G0=0,O_C0=O_G0+SZ_GF,O_Q0=O_C0+SZ_GF,O_G1=O_Q0+SZ_QF,O_GS=O_G1+SZ_GF;
constexpr size_t O_PJQ=O_GS+SZ_GF,O_PJK=O_PJQ+SZ_GF,O_AGG=O_PJK+SZ_GF,O_P1=O_AGG+SZ_GF;
constexpr size_t O_EQ=O_P1+SZ_GF,O_EK=O_EQ+32768,O_Q1=O_EK+32768,O_K1=O_Q1+32768;
constexpr size_t O_Q2=O_K1+32768,O_K2=O_Q2+32768,O_CSC=O_K2+32768,O_PS=O_CSC+32768,O_WT=O_PS+262144;
constexpr size_t O_BGC=O_WT+(size_t)3*2*512*512,O_BGQ=O_BGC+131072,O_PB=O_BGQ+32768;
constexpr size_t S_TOT=O_PB+(size_t)NB*HH*NG*NC;
__device__ float d_scratch[S_TOT];

__global__ void bitpack_k(const int* __restrict__ adj, unsigned* __restrict__ bits, int nwords){
    int w=blockIdx.x*256+threadIdx.x; if(w>=nwords) return;
    const int* p=adj+(size_t)w*32; unsigned v=0;
    #pragma unroll
    for(int i=0;i<32;i++) v|=(p[i]>0?1u:0u)<<i;
    bits[w]=v;
}
__global__ void repack_k(const float* __restrict__ W, float* __restrict__ out, int total){
    int i=blockIdx.x*256+threadIdx.x; if(i>=total) return;
    int d=i&63, f=(i>>6)&511, h=(i>>15)&7, l=i>>18;
    out[((size_t)(l*FF+f))*512+h*64+d]=W[i];
}
// e tables: raw, exp(e), exp(0.2e)
__global__ void dot_a_k(const float* __restrict__ X, const float* __restrict__ a,
                        float* __restrict__ raw, float* __restrict__ e1, float* __restrict__ e2, int N){
    int idx=blockIdx.x*256+threadIdx.x; if(idx>=NB*HH*N) return;
    int n=idx%N, h=(idx/N)%HH, b=idx/(N*HH);
    const float* xp=X+((size_t)(b*N+n))*FF+h*DD; const float* ap=a+h*DD;
    float s=0.f;
    #pragma unroll
    for(int i=0;i<DD;i+=4){
        float4 xv=*(const float4*)(xp+i); float4 av=*(const float4*)(ap+i);
        s+=xv.x*av.x+xv.y*av.y+xv.z*av.z+xv.w*av.w;
    }
    raw[idx]=s; e1[idx]=__expf(s); e2[idx]=__expf(0.2f*s);
}
// P~[bh][n][m] = bit ? (rq+rk>0 ? q1*k1 : q2*k2) : 0   (no exp in loop)
__global__ void pgen_k(const float* __restrict__ rq, const float* __restrict__ rk,
                       const float* __restrict__ q1, const float* __restrict__ k1,
                       const float* __restrict__ q2, const float* __restrict__ k2,
                       const unsigned* __restrict__ bits, float* __restrict__ P,
                       int Nn, int Mm, int orient, int bld){
    size_t idx=(size_t)blockIdx.x*256+threadIdx.x;
    if(idx>=(size_t)NB*HH*Nn*Mm) return;
    int m=(int)(idx%Mm); size_t r=idx/Mm;
    int n=(int)(r%Nn); int bh=(int)(r/Nn); int b=bh/HH;
    const unsigned* bb=bits+(size_t)b*NG*bld;
    unsigned bit;
    if(orient==1) bit=(bb[(size_t)m*bld+(n>>5)]>>(n&31))&1u;
    else          bit=(bb[(size_t)n*bld+(m>>5)]>>(m&31))&1u;
    float v=0.f;
    if(bit){
        int iq=bh*Nn+n, ik=bh*Mm+m;
        v=(rq[iq]+rk[ik]>0.f)?(q1[iq]*k1[ik]):(q2[iq]*k2[ik]);
    }
    P[idx]=v;
}
__global__ void colsum_k(const float* __restrict__ P, float* __restrict__ ps, int Nn, int Mm, int nch){
    int m=blockIdx.x*128+threadIdx.x, ch=blockIdx.y, bh=blockIdx.z;
    const float* p=P+(size_t)bh*Nn*Mm+(size_t)ch*128*Mm+m;
    float s=0.f;
    for(int n=0;n<128;n++) s+=p[(size_t)n*Mm];
    ps[((size_t)bh*Mm+m)*nch+ch]=s;
}
__global__ void csmerge_k(const float* __restrict__ ps, float* __restrict__ cs, int Mm, int nch){
    int idx=blockIdx.x*256+threadIdx.x; if(idx>=NB*HH*Mm) return;
    float s=0.f;
    for(int c=0;c<nch;c++) s+=ps[(size_t)idx*nch+c];
    cs[idx]=(s>0.f)?(1.f/s):0.f;
}

// ============ bf16-split mma.sync GEMM ============
struct GP {
    int M,N,K1,K2,Hdiv;
    const float *A1,*B1,*A2,*B2;
    int lda1,ldb1,lda2,ldb2,ldc;
    float* C;
    const float *E1,*E2,*scv;
    long long sA_b,sA_h,sB_b,sB_h,sC_b,sC_h,sSc;
    const unsigned* bits; int bld; long long sBits_b;
};
__device__ __forceinline__ void mma16816(float* c, const unsigned* a, const unsigned* b){
    asm volatile("mma.sync.aligned.m16n8k16.row.col.f32.bf16.bf16.f32 "
        "{%0,%1,%2,%3},{%4,%5,%6,%7},{%8,%9},{%0,%1,%2,%3};"
        : "+f"(c[0]),"+f"(c[1]),"+f"(c[2]),"+f"(c[3])
        : "r"(a[0]),"r"(a[1]),"r"(a[2]),"r"(a[3]),"r"(b[0]),"r"(b[1]));
}
constexpr int PAD=40, APL=128*PAD, BPL=64*PAD, SSTR=2*APL+2*BPL;
constexpr int SMB=2*SSTR*2;

template<int EPI>
__device__ __forceinline__ void epi_pair(float x0,float x1,float* cp,const float* e1,const float* e2){
    float2 o;
    if(EPI==0){ o.x=x0; o.y=x1; }
    else if(EPI==2){
        o.x=x0>0.f?x0:__expf(x0)-1.f; o.y=x1>0.f?x1:__expf(x1)-1.f;
    } else {
        float2 v1=*(const float2*)e1, v2=*(const float2*)e2; float f;
        f=1.f/(1.f+__expf(-x0)); o.x=v2.x+f*(v1.x-v2.x);
        f=1.f/(1.f+__expf(-x1)); o.y=v2.y+f*(v1.y-v2.y);
    }
    *(float2*)cp=o;
}

template<int ASRC,int EPI>
__global__ void __launch_bounds__(256) gemm_k(GP p){
    extern __shared__ __nv_bfloat16 sm[];
    const int t=threadIdx.x, lane=t&31, wid=t>>5;
    const int wm=wid&3, wn=wid>>2, g=lane>>2, tc=lane&3;
    const int m0=blockIdx.x*128, n0=blockIdx.y*64, z=blockIdx.z;
    const int zb=z/p.Hdiv, zh=z%p.Hdiv;
    const float* B1=p.B1+zb*p.sB_b+zh*p.sB_h;
    float* C=p.C+zb*p.sC_b+zh*p.sC_h;
    const float* A1=nullptr; const unsigned* bitsp=nullptr;
    if(ASRC==0) A1=p.A1+zb*p.sA_b+zh*p.sA_h;
    else        bitsp=p.bits+zb*p.sBits_b;
    const float* scv=(EPI==2)?(p.scv+(long long)z*p.sSc):nullptr;
    const int Ktot=p.K1+p.K2, niter=Ktot>>5;
    float acc[2][4][4]={};
    float rA[16], rB[8]; unsigned rW=0;
    const int ar=t>>1, akq=(t&1)*16;
    const int br=t>>3, bnq=(t&7)*8;
    const int wk=t&31, wsel=t>>5;

    auto loadregs=[&](int it){
        int kk=it<<5;
        if(ASRC==0){
            const float* Ap; int ldA,ko;
            if(kk<p.K1){Ap=A1; ldA=p.lda1; ko=kk;} else {Ap=p.A2; ldA=p.lda2; ko=kk-p.K1;}
            const float* s=Ap+(long long)(m0+ar)*ldA+ko+akq;
            #pragma unroll
            for(int q=0;q<4;q++) *(float4*)(rA+q*4)=*(const float4*)(s+q*4);
        } else {
            rW=bitsp[(long long)(kk+wk)*p.bld+((unsigned)m0>>5)+(wsel>>1)];
        }
        const float* Bp; int ldB,ko;
        if(kk<p.K1){Bp=B1; ldB=p.ldb1; ko=kk;} else {Bp=p.B2; ldB=p.ldb2; ko=kk-p.K1;}
        const float* s=Bp+(long long)(ko+br)*ldB+n0+bnq;
        *(float4*)(rB)=*(const float4*)(s);
        *(float4*)(rB+4)=*(const float4*)(s+4);
        if(EPI==2){
            float scl=scv[ko+br];
            #pragma unroll
            for(int i=0;i<8;i++) rB[i]*=scl;
        }
    };
    auto storesm=[&](int buf){
        __nv_bfloat16* Ah=sm+buf*SSTR; __nv_bfloat16* Al=Ah+APL;
        __nv_bfloat16* Bh=Ah+2*APL;    __nv_bfloat16* Bl=Bh+BPL;
        if(ASRC==0){
            #pragma unroll
            for(int i=0;i<16;i+=2){
                float x0=rA[i], x1=rA[i+1];
                __nv_bfloat16 h0=__float2bfloat16_rn(x0), h1=__float2bfloat16_rn(x1);
                __nv_bfloat16 l0=__float2bfloat16_rn(x0-__bfloat162float(h0));
                __nv_bfloat16 l1=__float2bfloat16_rn(x1-__bfloat162float(h1));
                int o=ar*PAD+akq+i;
                *(__nv_bfloat162*)(Ah+o)=__nv_bfloat162(h0,h1);
                *(__nv_bfloat162*)(Al+o)=__nv_bfloat162(l0,l1);
            }
        } else {
            int mb=wsel*16, sh=(wsel&1)*16;
            #pragma unroll
            for(int i=0;i<16;i++)
                Ah[(mb+i)*PAD+wk]=__float2bfloat16_rn((float)((rW>>(sh+i))&1u));
        }
        #pragma unroll
        for(int i=0;i<8;i++){
            float x=rB[i];
            __nv_bfloat16 h=__float2bfloat16_rn(x);
            Bh[(bnq+i)*PAD+br]=h;
            Bl[(bnq+i)*PAD+br]=__float2bfloat16_rn(x-__bfloat162float(h));
        }
    };

    loadregs(0);
    for(int it=0;it<niter;it++){
        int buf=it&1;
        storesm(buf);
        __syncthreads();
        if(it+1<niter) loadregs(it+1);
        __nv_bfloat16* Ah=sm+buf*SSTR; __nv_bfloat16* Al=Ah+APL;
        __nv_bfloat16* Bh=Ah+2*APL;    __nv_bfloat16* Bl=Bh+BPL;
        #pragma unroll
        for(int ks=0;ks<32;ks+=16){
            unsigned aH[2][4], aL[2][4], bH[4][2], bL[4][2];
            #pragma unroll
            for(int mt=0;mt<2;mt++){
                int r=(wm*32+mt*16+g)*PAD+ks+tc*2;
                aH[mt][0]=*(unsigned*)(Ah+r);        aH[mt][1]=*(unsigned*)(Ah+r+8*PAD);
                aH[mt][2]=*(unsigned*)(Ah+r+8);      aH[mt][3]=*(unsigned*)(Ah+r+8*PAD+8);
                if(ASRC==0){
                aL[mt][0]=*(unsigned*)(Al+r);        aL[mt][1]=*(unsigned*)(Al+r+8*PAD);
                aL[mt][2]=*(unsigned*)(Al+r+8);      aL[mt][3]=*(unsigned*)(Al+r+8*PAD+8); }
            }
            #pragma unroll
            for(int nt=0;nt<4;nt++){
                int r=(wn*32+nt*8+g)*PAD+ks+tc*2;
                bH[nt][0]=*(unsigned*)(Bh+r); bH[nt][1]=*(unsigned*)(Bh+r+8);
                bL[nt][0]=*(unsigned*)(Bl+r); bL[nt][1]=*(unsigned*)(Bl+r+8);
            }
            #pragma unroll
            for(int mt=0;mt<2;mt++)
                #pragma unroll
                for(int nt=0;nt<4;nt++){
                    mma16816(acc[mt][nt],aH[mt],bH[nt]);
                    mma16816(acc[mt][nt],aH[mt],bL[nt]);
                    if(ASRC==0) mma16816(acc[mt][nt],aL[mt],bH[nt]);
                }
        }
        __syncthreads();
    }
    #pragma unroll
    for(int mt=0;mt<2;mt++)
        #pragma unroll
        for(int nt=0;nt<4;nt++){
            long long r0=m0+wm*32+mt*16+g;
            int col=n0+wn*32+nt*8+tc*2;
            float* cp0=C+r0*p.ldc+col; float* cp1=C+(r0+8)*p.ldc+col;
            const float *e10=nullptr,*e20=nullptr,*e11=nullptr,*e21=nullptr;
            if(EPI==1){
                e10=p.E1+r0*p.ldc+col; e20=p.E2+r0*p.ldc+col;
                e11=p.E1+(r0+8)*p.ldc+col; e21=p.E2+(r0+8)*p.ldc+col;
            }
            epi_pair<EPI>(acc[mt][nt][0],acc[mt][nt][1],cp0,e10,e20);
            epi_pair<EPI>(acc[mt][nt][2],acc[mt][nt][3],cp1,e11,e21);
        }
}

static void gemm_go(int asrc,int epi,const GP& p,int zc){
    dim3 g(p.M/128,p.N/64,zc);
    if(asrc==1)      gemm_k<1,0><<<g,256,SMB>>>(p);
    else if(epi==0)  gemm_k<0,0><<<g,256,SMB>>>(p);
    else if(epi==1)  gemm_k<0,1><<<g,256,SMB>>>(p);
    else             gemm_k<0,2><<<g,256,SMB>>>(p);
}
static void proj_go(const float* X,int rows,const float* Wt,float* out){
    GP p{}; p.M=rows; p.N=512; p.K1=512; p.Hdiv=1;
    p.A1=X; p.lda1=512; p.B1=Wt; p.ldb1=512; p.C=out; p.ldc=512;
    gemm_go(0,0,p,1);
}
static void fusion_go(const float* a,const float* bm,int rows,const float* W,const float* U,
                      const float* Wf,const float* Uf,float* P1,float* out){
    GP p{}; p.M=rows; p.N=512; p.K1=512; p.K2=512; p.Hdiv=1;
    p.A1=a; p.lda1=512; p.B1=W; p.ldb1=512;
    p.A2=bm; p.lda2=512; p.B2=U; p.ldb2=512;
    p.C=P1; p.ldc=512;
    gemm_go(0,0,p,1);
    p.B1=Wf; p.B2=Uf; p.C=out; p.E1=P1; p.E2=a;
    gemm_go(0,1,p,1);
}
static void attn_go(float* S,const float* q,int Nqq,const float* kv,int Nkv,
                    const float* Wt,const float* a1,const float* a2,
                    int orient,const unsigned* bits,int bld,float* agg){
    float *projQ=S+O_PJQ,*projK=S+O_PJK;
    float *rq=S+O_EQ,*rk=S+O_EK,*q1=S+O_Q1,*k1=S+O_K1,*q2=S+O_Q2,*k2=S+O_K2;
    float *cs=S+O_CSC,*ps=S+O_PS,*P=S+O_PB;
    proj_go(q,NB*Nqq,Wt,projQ);
    proj_go(kv,NB*Nkv,Wt,projK);
    dot_a_k<<<(NB*HH*Nqq+255)/256,256>>>(projQ,a1,rq,q1,q2,Nqq);
    dot_a_k<<<(NB*HH*Nkv+255)/256,256>>>(projK,a2,rk,k1,k2,Nkv);
    { size_t tot=(size_t)NB*HH*Nqq*Nkv;
      pgen_k<<<(unsigned)((tot+255)/256),256>>>(rq,rk,q1,k1,q2,k2,bits,P,Nqq,Nkv,orient,bld); }
    int nch=Nqq/128;
    colsum_k<<<dim3(Nkv/128,nch,NB*HH),128>>>(P,ps,Nqq,Nkv,nch);
    csmerge_k<<<(NB*HH*Nkv+255)/256,256>>>(ps,cs,Nkv,nch);
    GP p{}; p.M=Nqq; p.N=64; p.K1=Nkv; p.Hdiv=HH;
    p.A1=P; p.lda1=Nkv; p.sA_b=(long long)HH*Nqq*Nkv; p.sA_h=(long long)Nqq*Nkv;
    p.B1=projK; p.ldb1=512; p.sB_b=(long long)Nkv*512; p.sB_h=64;
    p.C=agg; p.ldc=512; p.sC_b=(long long)Nqq*512; p.sC_h=64;
    p.scv=cs; p.sSc=Nkv;
    gemm_go(0,2,p,NB*HH);
}

extern "C" void kernel_launch(void* const* d_in, const int* in_sizes, int n_in,
                              void* d_out, int out_size){
    cudaFuncSetAttribute(gemm_k<0,0>,cudaFuncAttributeMaxDynamicSharedMemorySize,SMB);
    cudaFuncSetAttribute(gemm_k<0,1>,cudaFuncAttributeMaxDynamicSharedMemorySize,SMB);
    cudaFuncSetAttribute(gemm_k<0,2>,cudaFuncAttributeMaxDynamicSharedMemorySize,SMB);
    cudaFuncSetAttribute(gemm_k<1,0>,cudaFuncAttributeMaxDynamicSharedMemorySize,SMB);
    float* S; cudaGetSymbolAddress((void**)&S, d_scratch);
    const float* in_g=(const float*)d_in[0];
    const float* in_c=(const float*)d_in[1];
    const float* in_q=(const float*)d_in[2];
    const int* adj_gc=(const int*)d_in[3];
    const int* adj_gq=(const int*)d_in[4];
    const float* aW[3]={(const float*)d_in[5],(const float*)d_in[8],(const float*)d_in[11]};
    const float* aa1[3]={(const float*)d_in[6],(const float*)d_in[9],(const float*)d_in[12]};
    const float* aa2[3]={(const float*)d_in[7],(const float*)d_in[10],(const float*)d_in[13]};
    const float* fW=(const float*)d_in[14];
    const float* fU=(const float*)d_in[15];
    const float* fWf=(const float*)d_in[16];
    const float* fUf=(const float*)d_in[17];
    float* out=(float*)d_out;

    unsigned* bgc=(unsigned*)(S+O_BGC);
    unsigned* bgq=(unsigned*)(S+O_BGQ);
    float* Wt=S+O_WT;
    float *gsame=S+O_GS, *agg=S+O_AGG, *P1=S+O_P1, *G1tmp=S+O_G1;

    bitpack_k<<<512,256>>>(adj_gc,bgc,131072);
    bitpack_k<<<128,256>>>(adj_gq,bgq,32768);
    for(int tp=0;tp<3;tp++)
        repack_k<<<2048,256>>>(aW[tp],Wt+(size_t)tp*2*FF*512,2*HH*FF*DD);

    for(int l=0;l<2;l++){
        const float *Gin,*Cin,*Qin; float *Gout,*Cout,*Qout;
        if(l==0){ Gin=in_g; Cin=in_c; Qin=in_q; Gout=S+O_G0; Cout=S+O_C0; Qout=S+O_Q0; }
        else    { Gin=S+O_G0; Cin=S+O_C0; Qin=S+O_Q0;
                  Gout=out; Cout=out+SZ_GF; Qout=out+2*SZ_GF; }
        const float* fWl=fW+(size_t)l*4*FF*FF;  const float* fUl=fU+(size_t)l*4*FF*FF;
        const float* fWfl=fWf+(size_t)l*4*FF*FF; const float* fUfl=fUf+(size_t)l*4*FF*FF;
        {
            GP p{}; p.M=NC; p.N=512; p.K1=NG; p.Hdiv=1;
            p.bits=bgc; p.bld=NC/32; p.sBits_b=(long long)NG*(NC/32);
            p.B1=Gin; p.ldb1=512; p.sB_b=(long long)NG*512;
            p.C=gsame; p.ldc=512; p.sC_b=(long long)NC*512;
            gemm_go(1,0,p,NB);
        }
        fusion_go(Cin,gsame,NB*NC, fWl+0*FF*FF,fUl+0*FF*FF,fWfl+0*FF*FF,fUfl+0*FF*FF, P1,Cout);
        attn_go(S,Gin,NG,Cin,NC, Wt+(size_t)(0*2+l)*FF*512, aa1[0]+l*HH*DD, aa2[0]+l*HH*DD, 0,bgc,NC/32, agg);
        fusion_go(Gin,agg,NB*NG, fWl+1*FF*FF,fUl+1*FF*FF,fWfl+1*FF*FF,fUfl+1*FF*FF, P1,G1tmp);
        attn_go(S,Qin,NQ,Gin,NG, Wt+(size_t)(1*2+l)*FF*512, aa1[1]+l*HH*DD, aa2[1]+l*HH*DD, 1,bgq,NQ/32, agg);
        fusion_go(Qin,agg,NB*NQ, fWl+2*FF*FF,fUl+2*FF*FF,fWfl+2*FF*FF,fUfl+2*FF*FF, P1,Qout);
        attn_go(S,Gin,NG,Qin,NQ, Wt+(size_t)(2*2+l)*FF*512, aa1[2]+l*HH*DD, aa2[2]+l*HH*DD, 0,bgq,NQ/32, agg);
        fusion_go(G1tmp,agg,NB*NG, fWl+3*FF*FF,fUl+3*FF*FF,fWfl+3*FF*FF,fUfl+3*FF*FF, P1,Gout);
    }
}

// round 7
// speedup vs baseline: 1.0448x; 1.0448x over previous
#include <cuda_runtime.h>
#include <cuda_bf16.h>
#include <cstdint>

constexpr int NB=4, NG=1024, NC=1024, NQ=256, FF=512, HH=8, DD=64;
constexpr size_t SZ_GF=(size_t)NB*NG*FF, SZ_QF=(size_t)NB*NQ*FF;
constexpr size_t O_G0=0,O_C0=O_G0+SZ_GF,O_Q0=O_C0+SZ_GF,O_G1=O_Q0+SZ_QF,O_GS=O_G1+SZ_GF;
constexpr size_t O_PJQ=O_GS+SZ_GF,O_PJK=O_PJQ+SZ_GF,O_AGG=O_PJK+SZ_GF,O_P1=O_AGG+SZ_GF;
constexpr size_t O_EQ=O_P1+SZ_GF,O_EK=O_EQ+32768,O_Q1=O_EK+32768,O_K1=O_Q1+32768;
constexpr size_t O_Q2=O_K1+32768,O_K2=O_Q2+32768,O_CSC=O_K2+32768,O_PS=O_CSC+32768,O_WT=O_PS+262144;
constexpr size_t O_BGC=O_WT+(size_t)3*2*512*512,O_BGQ=O_BGC+131072,O_BGQT=O_BGQ+32768;
constexpr size_t S_TOT=O_BGQT+32768;
__device__ float d_scratch[S_TOT];

__global__ void bitpack_k(const int* __restrict__ adj, unsigned* __restrict__ bits, int nwords){
    int w=blockIdx.x*256+threadIdx.x; if(w>=nwords) return;
    const int* p=adj+(size_t)w*32; unsigned v=0;
    #pragma unroll
    for(int i=0;i<32;i++) v|=(p[i]>0?1u:0u)<<i;
    bits[w]=v;
}
// adj [NB][NG][NQ] -> bits[b][q][g>>5]
__global__ void bitpackT_k(const int* __restrict__ adj, unsigned* __restrict__ bits){
    int idx=blockIdx.x*256+threadIdx.x; if(idx>=NB*NQ*(NG/32)) return;
    int gw=idx&31, q=(idx>>5)&255, b=idx>>13;
    unsigned v=0;
    for(int i=0;i<32;i++) v|=(adj[((size_t)b*NG+gw*32+i)*NQ+q]>0?1u:0u)<<i;
    bits[(size_t)b*NQ*32+(size_t)q*32+gw]=v;
}
__global__ void repack3_k(const float* __restrict__ W0,const float* __restrict__ W1,
                          const float* __restrict__ W2, float* __restrict__ out){
    int i=blockIdx.x*256+threadIdx.x; if(i>=3*2*HH*FF*DD) return;
    int tp=i>>19, j=i&524287;
    int d=j&63, f=(j>>6)&511, h=(j>>15)&7, l=j>>18;
    const float* W=tp==0?W0:(tp==1?W1:W2);
    out[(size_t)tp*2*FF*512+((size_t)(l*FF+f))*512+h*64+d]=W[j];
}
__global__ void dot_a_k(const float* __restrict__ X, const float* __restrict__ a,
                        float* __restrict__ raw, float* __restrict__ e1, float* __restrict__ e2, int N){
    int idx=blockIdx.x*256+threadIdx.x; if(idx>=NB*HH*N) return;
    int n=idx%N, h=(idx/N)%HH, b=idx/(N*HH);
    const float* xp=X+((size_t)(b*N+n))*FF+h*DD; const float* ap=a+h*DD;
    float s=0.f;
    #pragma unroll
    for(int i=0;i<DD;i+=4){
        float4 xv=*(const float4*)(xp+i); float4 av=*(const float4*)(ap+i);
        s+=xv.x*av.x+xv.y*av.y+xv.z*av.z+xv.w*av.w;
    }
    raw[idx]=s; e1[idx]=__expf(s); e2[idx]=__expf(0.2f*s);
}
// s[m] partial over 256-query chunks, 8 heads/thread, bits-driven (no P buffer)
__global__ void bitsum_k(const unsigned* __restrict__ bits,
    const float* __restrict__ rq,const float* __restrict__ q1,const float* __restrict__ q2,
    const float* __restrict__ rk,const float* __restrict__ k1,const float* __restrict__ k2,
    float* __restrict__ ps, int Nn,int Mm,int bld,int nch,long long sb){
    __shared__ unsigned wb[32][4];
    __shared__ float qt[3][8][32];
    int t=threadIdx.x, m=blockIdx.x*128+t, b=blockIdx.z;
    int nbase=blockIdx.y*256;
    float acc[8]={}; float rkv[8],k1v[8],k2v[8];
    #pragma unroll
    for(int h=0;h<8;h++){ int bh=b*8+h; rkv[h]=rk[(size_t)bh*Mm+m]; k1v[h]=k1[(size_t)bh*Mm+m]; k2v[h]=k2[(size_t)bh*Mm+m]; }
    const unsigned* bb=bits+(size_t)b*sb+blockIdx.x*4;
    for(int n0=nbase;n0<nbase+256;n0+=32){
        wb[t>>2][t&3]=bb[(size_t)(n0+(t>>2))*bld+(t&3)];
        for(int i=t;i<768;i+=128){
            int which=i>>8, r=i&255, h=r>>5, nn=r&31;
            const float* src=which==0?rq:(which==1?q1:q2);
            qt[which][h][nn]=src[(size_t)(b*8+h)*Nn+n0+nn];
        }
        __syncthreads();
        int mw=t>>5, msh=t&31;
        for(int nn=0;nn<32;nn++){
            if((wb[nn][mw]>>msh)&1u){
                #pragma unroll
                for(int h=0;h<8;h++){
                    bool c=qt[0][h][nn]+rkv[h]>0.f;
                    acc[h]+= c? qt[1][h][nn]*k1v[h] : qt[2][h][nn]*k2v[h];
                }
            }
        }
        __syncthreads();
    }
    #pragma unroll
    for(int h=0;h<8;h++) ps[((size_t)(b*8+h)*Mm+m)*nch+blockIdx.y]=acc[h];
}
__global__ void csmerge_k(const float* __restrict__ ps, float* __restrict__ cs, int Mm, int nch){
    int idx=blockIdx.x*256+threadIdx.x; if(idx>=NB*HH*Mm) return;
    float s=0.f;
    for(int c=0;c<nch;c++) s+=ps[(size_t)idx*nch+c];
    cs[idx]=(s>0.f)?(1.f/s):0.f;
}

// ============ bf16-split mma.sync GEMM ============
struct GP {
    int M,N,K1,K2,Hdiv;
    const float *A1,*B1,*A2,*B2;
    int lda1,ldb1,lda2,ldb2,ldc;
    float* C;
    const float *E1,*E2,*scv;
    const float *qr,*qe1,*qe2,*kr,*ke1,*ke2;
    long long sA_b,sA_h,sB_b,sB_h,sC_b,sC_h,sSc;
    const unsigned* bits; int bld; long long sBits_b;
};
__device__ __forceinline__ void mma16816(float* c, const unsigned* a, const unsigned* b){
    asm volatile("mma.sync.aligned.m16n8k16.row.col.f32.bf16.bf16.f32 "
        "{%0,%1,%2,%3},{%4,%5,%6,%7},{%8,%9},{%0,%1,%2,%3};"
        : "+f"(c[0]),"+f"(c[1]),"+f"(c[2]),"+f"(c[3])
        : "r"(a[0]),"r"(a[1]),"r"(a[2]),"r"(a[3]),"r"(b[0]),"r"(b[1]));
}
constexpr int PAD=40, APL=128*PAD, BPL=64*PAD, SSTR=2*APL+2*BPL;
constexpr int SMB=2*SSTR*2+3*1024*4;  // buffers + k-tables

template<int EPI>
__device__ __forceinline__ void epi_pair(float x0,float x1,float* cp,const float* e1,const float* e2){
    float2 o;
    if(EPI==0){ o.x=x0; o.y=x1; }
    else if(EPI==2){
        o.x=x0>0.f?x0:__expf(x0)-1.f; o.y=x1>0.f?x1:__expf(x1)-1.f;
    } else {
        float2 v1=*(const float2*)e1, v2=*(const float2*)e2; float f;
        f=1.f/(1.f+__expf(-x0)); o.x=v2.x+f*(v1.x-v2.x);
        f=1.f/(1.f+__expf(-x1)); o.y=v2.y+f*(v1.y-v2.y);
    }
    *(float2*)cp=o;
}

template<int ASRC,int EPI>
__global__ void __launch_bounds__(256) gemm_k(GP p){
    extern __shared__ __nv_bfloat16 sm[];
    const int t=threadIdx.x, lane=t&31, wid=t>>5;
    const int wm=wid&3, wn=wid>>2, g=lane>>2, tc=lane&3;
    const int m0=blockIdx.x*128, n0=blockIdx.y*64, z=blockIdx.z;
    const int zb=z/p.Hdiv, zh=z%p.Hdiv;
    const float* B1=p.B1+zb*p.sB_b+zh*p.sB_h;
    float* C=p.C+zb*p.sC_b+zh*p.sC_h;
    const float* A1=nullptr; const unsigned* bitsp=nullptr;
    if(ASRC==0) A1=p.A1+zb*p.sA_b+zh*p.sA_h;
    else        bitsp=p.bits+zb*p.sBits_b;
    const float* scv=(EPI==2)?(p.scv+(long long)z*p.sSc):nullptr;
    const int Ktot=p.K1+p.K2, niter=Ktot>>5;
    float acc[2][4][4]={};
    float rA[16], rB[8]; unsigned rW=0;
    const int ar=t>>1, akq=(t&1)*16;
    const int br=t>>3, bnq=(t&7)*8;
    const int wk=t&31, wsel=t>>5;
    float rqv=0.f,q1v=0.f,q2v=0.f;
    float* kt=(float*)(sm+2*SSTR);
    if(ASRC==2){
        long long qo=(long long)z*p.M; int n=m0+ar;
        rqv=p.qr[qo+n]; q1v=p.qe1[qo+n]; q2v=p.qe2[qo+n];
        long long ko=(long long)z*p.K1;
        for(int i=t;i<p.K1;i+=256){
            kt[i]=p.kr[ko+i]; kt[p.K1+i]=p.ke1[ko+i]; kt[2*p.K1+i]=p.ke2[ko+i];
        }
        __syncthreads();
    }

    auto loadregs=[&](int it){
        int kk=it<<5;
        if(ASRC==0){
            const float* Ap; int ldA,ko;
            if(kk<p.K1){Ap=A1; ldA=p.lda1; ko=kk;} else {Ap=p.A2; ldA=p.lda2; ko=kk-p.K1;}
            const float* s=Ap+(long long)(m0+ar)*ldA+ko+akq;
            #pragma unroll
            for(int q=0;q<4;q++) *(float4*)(rA+q*4)=*(const float4*)(s+q*4);
        } else if(ASRC==1){
            rW=bitsp[(long long)(kk+wk)*p.bld+((unsigned)m0>>5)+(wsel>>1)];
        } else {
            rW=bitsp[(size_t)(m0+ar)*p.bld+(kk>>5)];
        }
        const float* Bp; int ldB,ko;
        if(kk<p.K1){Bp=B1; ldB=p.ldb1; ko=kk;} else {Bp=p.B2; ldB=p.ldb2; ko=kk-p.K1;}
        const float* s=Bp+(long long)(ko+br)*ldB+n0+bnq;
        *(float4*)(rB)=*(const float4*)(s);
        *(float4*)(rB+4)=*(const float4*)(s+4);
        if(EPI==2){
            float scl=scv[ko+br];
            #pragma unroll
            for(int i=0;i<8;i++) rB[i]*=scl;
        }
    };
    auto storesm=[&](int buf,int kk){
        __nv_bfloat16* Ah=sm+buf*SSTR; __nv_bfloat16* Al=Ah+APL;
        __nv_bfloat16* Bh=Ah+2*APL;    __nv_bfloat16* Bl=Bh+BPL;
        if(ASRC==0){
            #pragma unroll
            for(int i=0;i<16;i+=2){
                float x0=rA[i], x1=rA[i+1];
                __nv_bfloat16 h0=__float2bfloat16_rn(x0), h1=__float2bfloat16_rn(x1);
                __nv_bfloat16 l0=__float2bfloat16_rn(x0-__bfloat162float(h0));
                __nv_bfloat16 l1=__float2bfloat16_rn(x1-__bfloat162float(h1));
                int o=ar*PAD+akq+i;
                *(__nv_bfloat162*)(Ah+o)=__nv_bfloat162(h0,h1);
                *(__nv_bfloat162*)(Al+o)=__nv_bfloat162(l0,l1);
            }
        } else if(ASRC==1){
            int mb=wsel*16, sh=(wsel&1)*16;
            #pragma unroll
            for(int i=0;i<16;i++)
                Ah[(mb+i)*PAD+wk]=__float2bfloat16_rn((float)((rW>>(sh+i))&1u));
        } else {
            #pragma unroll
            for(int i=0;i<16;i++){
                float v=0.f;
                if((rW>>(akq+i))&1u){
                    int mI=kk+akq+i;
                    v=(rqv+kt[mI]>0.f)?(q1v*kt[p.K1+mI]):(q2v*kt[2*p.K1+mI]);
                }
                __nv_bfloat16 h=__float2bfloat16_rn(v);
                int o=ar*PAD+akq+i;
                Ah[o]=h; Al[o]=__float2bfloat16_rn(v-__bfloat162float(h));
            }
        }
        #pragma unroll
        for(int i=0;i<8;i++){
            float x=rB[i];
            __nv_bfloat16 h=__float2bfloat16_rn(x);
            Bh[(bnq+i)*PAD+br]=h;
            Bl[(bnq+i)*PAD+br]=__float2bfloat16_rn(x-__bfloat162float(h));
        }
    };

    loadregs(0);
    for(int it=0;it<niter;it++){
        int buf=it&1;
        storesm(buf,it<<5);
        __syncthreads();
        if(it+1<niter) loadregs(it+1);
        __nv_bfloat16* Ah=sm+buf*SSTR; __nv_bfloat16* Al=Ah+APL;
        __nv_bfloat16* Bh=Ah+2*APL;    __nv_bfloat16* Bl=Bh+BPL;
        #pragma unroll
        for(int ks=0;ks<32;ks+=16){
            unsigned aH[2][4], aL[2][4], bH[4][2], bL[4][2];
            #pragma unroll
            for(int mt=0;mt<2;mt++){
                int r=(wm*32+mt*16+g)*PAD+ks+tc*2;
                aH[mt][0]=*(unsigned*)(Ah+r);        aH[mt][1]=*(unsigned*)(Ah+r+8*PAD);
                aH[mt][2]=*(unsigned*)(Ah+r+8);      aH[mt][3]=*(unsigned*)(Ah+r+8*PAD+8);
                if(ASRC!=1){
                aL[mt][0]=*(unsigned*)(Al+r);        aL[mt][1]=*(unsigned*)(Al+r+8*PAD);
                aL[mt][2]=*(unsigned*)(Al+r+8);      aL[mt][3]=*(unsigned*)(Al+r+8*PAD+8); }
            }
            #pragma unroll
            for(int nt=0;nt<4;nt++){
                int r=(wn*32+nt*8+g)*PAD+ks+tc*2;
                bH[nt][0]=*(unsigned*)(Bh+r); bH[nt][1]=*(unsigned*)(Bh+r+8);
                bL[nt][0]=*(unsigned*)(Bl+r); bL[nt][1]=*(unsigned*)(Bl+r+8);
            }
            #pragma unroll
            for(int mt=0;mt<2;mt++)
                #pragma unroll
                for(int nt=0;nt<4;nt++){
                    mma16816(acc[mt][nt],aH[mt],bH[nt]);
                    mma16816(acc[mt][nt],aH[mt],bL[nt]);
                    if(ASRC!=1) mma16816(acc[mt][nt],aL[mt],bH[nt]);
                }
        }
        __syncthreads();
    }
    #pragma unroll
    for(int mt=0;mt<2;mt++)
        #pragma unroll
        for(int nt=0;nt<4;nt++){
            long long r0=m0+wm*32+mt*16+g;
            int col=n0+wn*32+nt*8+tc*2;
            float* cp0=C+r0*p.ldc+col; float* cp1=C+(r0+8)*p.ldc+col;
            const float *e10=nullptr,*e20=nullptr,*e11=nullptr,*e21=nullptr;
            if(EPI==1){
                e10=p.E1+r0*p.ldc+col; e20=p.E2+r0*p.ldc+col;
                e11=p.E1+(r0+8)*p.ldc+col; e21=p.E2+(r0+8)*p.ldc+col;
            }
            epi_pair<EPI>(acc[mt][nt][0],acc[mt][nt][1],cp0,e10,e20);
            epi_pair<EPI>(acc[mt][nt][2],acc[mt][nt][3],cp1,e11,e21);
        }
}

static void gemm_go(int asrc,int epi,const GP& p,int zc){
    dim3 g(p.M/128,p.N/64,zc);
    if(asrc==1)      gemm_k<1,0><<<g,256,SMB>>>(p);
    else if(asrc==2) gemm_k<2,2><<<g,256,SMB>>>(p);
    else if(epi==0)  gemm_k<0,0><<<g,256,SMB>>>(p);
    else if(epi==1)  gemm_k<0,1><<<g,256,SMB>>>(p);
    else             gemm_k<0,2><<<g,256,SMB>>>(p);
}
static void proj_go(const float* X,int rows,const float* Wt,float* out){
    GP p{}; p.M=rows; p.N=512; p.K1=512; p.Hdiv=1;
    p.A1=X; p.lda1=512; p.B1=Wt; p.ldb1=512; p.C=out; p.ldc=512;
    gemm_go(0,0,p,1);
}
static void fusion_go(const float* a,const float* bm,int rows,const float* W,const float* U,
                      const float* Wf,const float* Uf,float* P1,float* out){
    GP p{}; p.M=rows; p.N=512; p.K1=512; p.K2=512; p.Hdiv=1;
    p.A1=a; p.lda1=512; p.B1=W; p.ldb1=512;
    p.A2=bm; p.lda2=512; p.B2=U; p.ldb2=512;
    p.C=P1; p.ldc=512;
    gemm_go(0,0,p,1);
    p.B1=Wf; p.B2=Uf; p.C=out; p.E1=P1; p.E2=a;
    gemm_go(0,1,p,1);
}
static void attn_go(float* S,const float* q,int Nqq,const float* kv,int Nkv,
                    const float* Wt,const float* a1,const float* a2,
                    const unsigned* bits,int bld,long long sb,float* agg){
    float *projQ=S+O_PJQ,*projK=S+O_PJK;
    float *rq=S+O_EQ,*rk=S+O_EK,*q1=S+O_Q1,*k1=S+O_K1,*q2=S+O_Q2,*k2=S+O_K2;
    float *cs=S+O_CSC,*ps=S+O_PS;
    proj_go(q,NB*Nqq,Wt,projQ);
    proj_go(kv,NB*Nkv,Wt,projK);
    dot_a_k<<<(NB*HH*Nqq+255)/256,256>>>(projQ,a1,rq,q1,q2,Nqq);
    dot_a_k<<<(NB*HH*Nkv+255)/256,256>>>(projK,a2,rk,k1,k2,Nkv);
    int nch=Nqq/256;
    bitsum_k<<<dim3(Nkv/128,nch,NB),128>>>(bits,rq,q1,q2,rk,k1,k2,ps,Nqq,Nkv,bld,nch,sb);
    csmerge_k<<<(NB*HH*Nkv+255)/256,256>>>(ps,cs,Nkv,nch);
    GP p{}; p.M=Nqq; p.N=64; p.K1=Nkv; p.Hdiv=HH;
    p.B1=projK; p.ldb1=512; p.sB_b=(long long)Nkv*512; p.sB_h=64;
    p.C=agg; p.ldc=512; p.sC_b=(long long)Nqq*512; p.sC_h=64;
    p.scv=cs; p.sSc=Nkv;
    p.qr=rq; p.qe1=q1; p.qe2=q2; p.kr=rk; p.ke1=k1; p.ke2=k2;
    p.bits=bits; p.bld=bld; p.sBits_b=sb;
    gemm_go(2,2,p,NB*HH);
}

extern "C" void kernel_launch(void* const* d_in, const int* in_sizes, int n_in,
                              void* d_out, int out_size){
    cudaFuncSetAttribute(gemm_k<0,0>,cudaFuncAttributeMaxDynamicSharedMemorySize,SMB);
    cudaFuncSetAttribute(gemm_k<0,1>,cudaFuncAttributeMaxDynamicSharedMemorySize,SMB);
    cudaFuncSetAttribute(gemm_k<2,2>,cudaFuncAttributeMaxDynamicSharedMemorySize,SMB);
    cudaFuncSetAttribute(gemm_k<1,0>,cudaFuncAttributeMaxDynamicSharedMemorySize,SMB);
    float* S; cudaGetSymbolAddress((void**)&S, d_scratch);
    const float* in_g=(const float*)d_in[0];
    const float* in_c=(const float*)d_in[1];
    const float* in_q=(const float*)d_in[2];
    const int* adj_gc=(const int*)d_in[3];
    const int* adj_gq=(const int*)d_in[4];
    const float* aW[3]={(const float*)d_in[5],(const float*)d_in[8],(const float*)d_in[11]};
    const float* aa1[3]={(const float*)d_in[6],(const float*)d_in[9],(const float*)d_in[12]};
    const float* aa2[3]={(const float*)d_in[7],(const float*)d_in[10],(const float*)d_in[13]};
    const float* fW=(const float*)d_in[14];
    const float* fU=(const float*)d_in[15];
    const float* fWf=(const float*)d_in[16];
    const float* fUf=(const float*)d_in[17];
    float* out=(float*)d_out;

    unsigned* bgc=(unsigned*)(S+O_BGC);
    unsigned* bgq=(unsigned*)(S+O_BGQ);
    unsigned* bgqT=(unsigned*)(S+O_BGQT);
    float* Wt=S+O_WT;
    float *gsame=S+O_GS, *agg=S+O_AGG, *P1=S+O_P1, *G1tmp=S+O_G1;

    bitpack_k<<<512,256>>>(adj_gc,bgc,131072);
    bitpack_k<<<128,256>>>(adj_gq,bgq,32768);
    bitpackT_k<<<128,256>>>(adj_gq,bgqT);
    repack3_k<<<(3*2*HH*FF*DD+255)/256,256>>>(aW[0],aW[1],aW[2],Wt);

    for(int l=0;l<2;l++){
        const float *Gin,*Cin,*Qin; float *Gout,*Cout,*Qout;
        if(l==0){ Gin=in_g; Cin=in_c; Qin=in_q; Gout=S+O_G0; Cout=S+O_C0; Qout=S+O_Q0; }
        else    { Gin=S+O_G0; Cin=S+O_C0; Qin=S+O_Q0;
                  Gout=out; Cout=out+SZ_GF; Qout=out+2*SZ_GF; }
        const float* fWl=fW+(size_t)l*4*FF*FF;  const float* fUl=fU+(size_t)l*4*FF*FF;
        const float* fWfl=fWf+(size_t)l*4*FF*FF; const float* fUfl=fUf+(size_t)l*4*FF*FF;
        {
            GP p{}; p.M=NC; p.N=512; p.K1=NG; p.Hdiv=1;
            p.bits=bgc; p.bld=NC/32; p.sBits_b=(long long)NG*(NC/32);
            p.B1=Gin; p.ldb1=512; p.sB_b=(long long)NG*512;
            p.C=gsame; p.ldc=512; p.sC_b=(long long)NC*512;
            gemm_go(1,0,p,NB);
        }
        fusion_go(Cin,gsame,NB*NC, fWl+0*FF*FF,fUl+0*FF*FF,fWfl+0*FF*FF,fUfl+0*FF*FF, P1,Cout);
        attn_go(S,Gin,NG,Cin,NC, Wt+(size_t)(0*2+l)*FF*512, aa1[0]+l*HH*DD, aa2[0]+l*HH*DD,
                bgc,NC/32,(long long)NG*(NC/32), agg);
        fusion_go(Gin,agg,NB*NG, fWl+1*FF*FF,fUl+1*FF*FF,fWfl+1*FF*FF,fUfl+1*FF*FF, P1,G1tmp);
        attn_go(S,Qin,NQ,Gin,NG, Wt+(size_t)(1*2+l)*FF*512, aa1[1]+l*HH*DD, aa2[1]+l*HH*DD,
                bgqT,NG/32,(long long)NQ*(NG/32), agg);
        fusion_go(Qin,agg,NB*NQ, fWl+2*FF*FF,fUl+2*FF*FF,fWfl+2*FF*FF,fUfl+2*FF*FF, P1,Qout);
        attn_go(S,Gin,NG,Qin,NQ, Wt+(size_t)(2*2+l)*FF*512, aa1[2]+l*HH*DD, aa2[2]+l*HH*DD,
                bgq,NQ/32,(long long)NG*(NQ/32), agg);
        fusion_go(G1tmp,agg,NB*NG, fWl+3*FF*FF,fUl+3*FF*FF,fWfl+3*FF*FF,fUfl+3*FF*FF, P1,Gout);
    }
}

// round 8
// speedup vs baseline: 1.4164x; 1.3557x over previous
#include <cuda_runtime.h>
#include <cuda_bf16.h>
#include <cstdint>

constexpr int NB=4, NG=1024, NC=1024, NQ=256, FF=512, HH=8, DD=64;
constexpr size_t SZ_GF=(size_t)NB*NG*FF, SZ_QF=(size_t)NB*NQ*FF;
constexpr size_t O_G0=0,O_C0=O_G0+SZ_GF,O_Q0=O_C0+SZ_GF,O_G1=O_Q0+SZ_QF,O_GS=O_G1+SZ_GF;
constexpr size_t O_PJQ=O_GS+SZ_GF,O_PJK=O_PJQ+SZ_GF,O_AGG=O_PJK+SZ_GF,O_P1=O_AGG+SZ_GF;
constexpr size_t O_EQ=O_P1+SZ_GF,O_EK=O_EQ+32768,O_Q1=O_EK+32768,O_K1=O_Q1+32768;
constexpr size_t O_Q2=O_K1+32768,O_K2=O_Q2+32768,O_CSC=O_K2+32768,O_PS=O_CSC+32768,O_WT=O_PS+262144;
constexpr size_t O_BGC=O_WT+(size_t)3*2*512*512,O_BGQ=O_BGC+131072,O_BGQT=O_BGQ+32768;
constexpr size_t S_TOT=O_BGQT+32768;
__device__ float d_scratch[S_TOT];

__global__ void bitpack_k(const int* __restrict__ adj, unsigned* __restrict__ bits, int nwords){
    int w=blockIdx.x*256+threadIdx.x; if(w>=nwords) return;
    const int* p=adj+(size_t)w*32; unsigned v=0;
    #pragma unroll
    for(int i=0;i<32;i++) v|=(p[i]>0?1u:0u)<<i;
    bits[w]=v;
}
__global__ void bitpackT_k(const int* __restrict__ adj, unsigned* __restrict__ bits){
    int idx=blockIdx.x*256+threadIdx.x; if(idx>=NB*NQ*(NG/32)) return;
    int gw=idx&31, q=(idx>>5)&255, b=idx>>13;
    unsigned v=0;
    for(int i=0;i<32;i++) v|=(adj[((size_t)b*NG+gw*32+i)*NQ+q]>0?1u:0u)<<i;
    bits[(size_t)b*NQ*32+(size_t)q*32+gw]=v;
}
__global__ void repack3_k(const float* __restrict__ W0,const float* __restrict__ W1,
                          const float* __restrict__ W2, float* __restrict__ out){
    int i=blockIdx.x*256+threadIdx.x; if(i>=3*2*HH*FF*DD) return;
    int tp=i>>19, j=i&524287;
    int d=j&63, f=(j>>6)&511, h=(j>>15)&7, l=j>>18;
    const float* W=tp==0?W0:(tp==1?W1:W2);
    out[(size_t)tp*2*FF*512+((size_t)(l*FF+f))*512+h*64+d]=W[j];
}
__global__ void dot_a_k(const float* __restrict__ X, const float* __restrict__ a,
                        float* __restrict__ raw, float* __restrict__ e1, float* __restrict__ e2, int N){
    int idx=blockIdx.x*256+threadIdx.x; if(idx>=NB*HH*N) return;
    int n=idx%N, h=(idx/N)%HH, b=idx/(N*HH);
    const float* xp=X+((size_t)(b*N+n))*FF+h*DD; const float* ap=a+h*DD;
    float s=0.f;
    #pragma unroll
    for(int i=0;i<DD;i+=4){
        float4 xv=*(const float4*)(xp+i); float4 av=*(const float4*)(ap+i);
        s+=xv.x*av.x+xv.y*av.y+xv.z*av.z+xv.w*av.w;
    }
    raw[idx]=s; e1[idx]=__expf(s); e2[idx]=__expf(0.2f*s);
}
__global__ void bitsum_k(const unsigned* __restrict__ bits,
    const float* __restrict__ rq,const float* __restrict__ q1,const float* __restrict__ q2,
    const float* __restrict__ rk,const float* __restrict__ k1,const float* __restrict__ k2,
    float* __restrict__ ps, int Nn,int Mm,int bld,int nch,long long sb){
    __shared__ unsigned wb[32][4];
    __shared__ float qt[3][8][32];
    int t=threadIdx.x, m=blockIdx.x*128+t, b=blockIdx.z;
    int nbase=blockIdx.y*256;
    float acc[8]={}; float rkv[8],k1v[8],k2v[8];
    #pragma unroll
    for(int h=0;h<8;h++){ int bh=b*8+h; rkv[h]=rk[(size_t)bh*Mm+m]; k1v[h]=k1[(size_t)bh*Mm+m]; k2v[h]=k2[(size_t)bh*Mm+m]; }
    const unsigned* bb=bits+(size_t)b*sb+blockIdx.x*4;
    for(int n0=nbase;n0<nbase+256;n0+=32){
        wb[t>>2][t&3]=bb[(size_t)(n0+(t>>2))*bld+(t&3)];
        for(int i=t;i<768;i+=128){
            int which=i>>8, r=i&255, h=r>>5, nn=r&31;
            const float* src=which==0?rq:(which==1?q1:q2);
            qt[which][h][nn]=src[(size_t)(b*8+h)*Nn+n0+nn];
        }
        __syncthreads();
        int mw=t>>5, msh=t&31;
        for(int nn=0;nn<32;nn++){
            if((wb[nn][mw]>>msh)&1u){
                #pragma unroll
                for(int h=0;h<8;h++){
                    bool c=qt[0][h][nn]+rkv[h]>0.f;
                    acc[h]+= c? qt[1][h][nn]*k1v[h] : qt[2][h][nn]*k2v[h];
                }
            }
        }
        __syncthreads();
    }
    #pragma unroll
    for(int h=0;h<8;h++) ps[((size_t)(b*8+h)*Mm+m)*nch+blockIdx.y]=acc[h];
}
__global__ void csmerge_k(const float* __restrict__ ps, float* __restrict__ cs, int Mm, int nch){
    int idx=blockIdx.x*256+threadIdx.x; if(idx>=NB*HH*Mm) return;
    float s=0.f;
    for(int c=0;c<nch;c++) s+=ps[(size_t)idx*nch+c];
    cs[idx]=(s>0.f)?(1.f/s):0.f;
}

// ============ bf16-split mma.sync GEMM with ldmatrix ============
struct GP {
    int M,N,K1,K2,Hdiv;
    const float *A1,*B1,*A2,*B2;
    int lda1,ldb1,lda2,ldb2,ldc;
    float* C;
    const float *E1,*E2,*scv;
    const float *qr,*qe1,*qe2,*kr,*ke1,*ke2;
    long long sA_b,sA_h,sB_b,sB_h,sC_b,sC_h,sSc;
    const unsigned* bits; int bld; long long sBits_b;
};
__device__ __forceinline__ void mma16816(float* c, const unsigned* a, const unsigned* b){
    asm volatile("mma.sync.aligned.m16n8k16.row.col.f32.bf16.bf16.f32 "
        "{%0,%1,%2,%3},{%4,%5,%6,%7},{%8,%9},{%0,%1,%2,%3};"
        : "+f"(c[0]),"+f"(c[1]),"+f"(c[2]),"+f"(c[3])
        : "r"(a[0]),"r"(a[1]),"r"(a[2]),"r"(a[3]),"r"(b[0]),"r"(b[1]));
}
#define LDSM4(d,a) asm volatile("ldmatrix.sync.aligned.m8n8.x4.shared.b16 {%0,%1,%2,%3},[%4];":"=r"((d)[0]),"=r"((d)[1]),"=r"((d)[2]),"=r"((d)[3]):"r"(a))
#define LDSM4T(d,a) asm volatile("ldmatrix.sync.aligned.m8n8.x4.trans.shared.b16 {%0,%1,%2,%3},[%4];":"=r"((d)[0]),"=r"((d)[1]),"=r"((d)[2]),"=r"((d)[3]):"r"(a))
// A: [128 m][32 k] halves, swizzle f=(r>>1)&3 ; B: [32 k][64 n] halves, f=r&7
#define SWZA(r,c) (((r)<<5)+((((c)>>3)^(((r)>>1)&3))<<3)+((c)&7))
#define SWZB(r,c) (((r)<<6)+((((c)>>3)^((r)&7))<<3)+((c)&7))
constexpr int A_H=128*32, B_H=32*64;
constexpr int OFF_AL=A_H, OFF_BH=2*A_H, OFF_BL=2*A_H+B_H;
constexpr int SSTR=2*A_H+2*B_H;               // halves per buffer
constexpr int SMB=2*SSTR*2+3*1024*4;

template<int EPI>
__device__ __forceinline__ void epi_pair(float x0,float x1,float* cp,const float* e1,const float* e2){
    float2 o;
    if(EPI==0){ o.x=x0; o.y=x1; }
    else if(EPI==2){
        o.x=x0>0.f?x0:__expf(x0)-1.f; o.y=x1>0.f?x1:__expf(x1)-1.f;
    } else {
        float2 v1=*(const float2*)e1, v2=*(const float2*)e2; float f;
        f=1.f/(1.f+__expf(-x0)); o.x=v2.x+f*(v1.x-v2.x);
        f=1.f/(1.f+__expf(-x1)); o.y=v2.y+f*(v1.y-v2.y);
    }
    *(float2*)cp=o;
}

template<int ASRC,int EPI>
__global__ void __launch_bounds__(256) gemm_k(GP p){
    extern __shared__ __nv_bfloat16 sm[];
    const int t=threadIdx.x, lane=t&31, wid=t>>5;
    const int wm=wid&3, wn=wid>>2, g=lane>>2, tc=lane&3;
    const int m0=blockIdx.x*128, n0=blockIdx.y*64, z=blockIdx.z;
    const int zb=z/p.Hdiv, zh=z%p.Hdiv;
    const float* B1=p.B1+zb*p.sB_b+zh*p.sB_h;
    float* C=p.C+zb*p.sC_b+zh*p.sC_h;
    const float* A1=nullptr; const unsigned* bitsp=nullptr;
    if(ASRC==0) A1=p.A1+zb*p.sA_b+zh*p.sA_h;
    else        bitsp=p.bits+zb*p.sBits_b;
    const float* scv=(EPI==2)?(p.scv+(long long)z*p.sSc):nullptr;
    const int Ktot=p.K1+p.K2, niter=Ktot>>5;
    float acc[2][4][4]={};
    float rA[16], rB[8]; unsigned rW=0;
    const int ar=t>>1, akq=(t&1)*16;
    const int br=t>>3, bnq=(t&7)*8;
    const int wk=t&31, wsel=t>>5;
    float rqv=0.f,q1v=0.f,q2v=0.f;
    float* kt=(float*)(sm+2*SSTR);
    unsigned smb=(unsigned)__cvta_generic_to_shared(sm);
    // ldmatrix addresses (byte, buffer 0)
    unsigned aAddr[2][2], bAddr[2][2];
    {
        int rA_=wm*32+(lane&15), cgA=(lane>>4)*8;
        #pragma unroll
        for(int mt=0;mt<2;mt++)
            #pragma unroll
            for(int k2=0;k2<2;k2++) aAddr[mt][k2]=smb+2u*SWZA(rA_+mt*16, cgA+k2*16);
        int rB_=(lane&7)+((lane>>3)&1)*8, cB=wn*32+(lane>>4)*8;
        #pragma unroll
        for(int pp=0;pp<2;pp++)
            #pragma unroll
            for(int k2=0;k2<2;k2++) bAddr[pp][k2]=smb+2u*(OFF_BH+SWZB(rB_+k2*16, cB+pp*16));
    }
    if(ASRC==2){
        long long qo=(long long)z*p.M; int n=m0+ar;
        rqv=p.qr[qo+n]; q1v=p.qe1[qo+n]; q2v=p.qe2[qo+n];
        long long ko=(long long)z*p.K1;
        for(int i=t;i<p.K1;i+=256){
            kt[i]=p.kr[ko+i]; kt[p.K1+i]=p.ke1[ko+i]; kt[2*p.K1+i]=p.ke2[ko+i];
        }
        __syncthreads();
    }

    auto loadregs=[&](int it){
        int kk=it<<5;
        if(ASRC==0){
            const float* Ap; int ldA,ko;
            if(kk<p.K1){Ap=A1; ldA=p.lda1; ko=kk;} else {Ap=p.A2; ldA=p.lda2; ko=kk-p.K1;}
            const float* s=Ap+(long long)(m0+ar)*ldA+ko+akq;
            #pragma unroll
            for(int q=0;q<4;q++) *(float4*)(rA+q*4)=*(const float4*)(s+q*4);
        } else if(ASRC==1){
            rW=bitsp[(long long)(kk+wk)*p.bld+((unsigned)m0>>5)+(wsel>>1)];
        } else {
            rW=bitsp[(size_t)(m0+ar)*p.bld+(kk>>5)];
        }
        const float* Bp; int ldB,ko;
        if(kk<p.K1){Bp=B1; ldB=p.ldb1; ko=kk;} else {Bp=p.B2; ldB=p.ldb2; ko=kk-p.K1;}
        const float* s=Bp+(long long)(ko+br)*ldB+n0+bnq;
        *(float4*)(rB)=*(const float4*)(s);
        *(float4*)(rB+4)=*(const float4*)(s+4);
        if(EPI==2){
            float scl=scv[ko+br];
            #pragma unroll
            for(int i=0;i<8;i++) rB[i]*=scl;
        }
    };
    auto storesm=[&](int buf,int kk){
        __nv_bfloat16* base=sm+buf*SSTR;
        if(ASRC==0){
            #pragma unroll
            for(int i=0;i<16;i+=2){
                float x0=rA[i], x1=rA[i+1];
                __nv_bfloat16 h0=__float2bfloat16_rn(x0), h1=__float2bfloat16_rn(x1);
                __nv_bfloat16 l0=__float2bfloat16_rn(x0-__bfloat162float(h0));
                __nv_bfloat16 l1=__float2bfloat16_rn(x1-__bfloat162float(h1));
                int o=SWZA(ar,akq+i);
                *(__nv_bfloat162*)(base+o)=__nv_bfloat162(h0,h1);
                *(__nv_bfloat162*)(base+OFF_AL+o)=__nv_bfloat162(l0,l1);
            }
        } else if(ASRC==1){
            int mb=wsel*16, sh=(wsel&1)*16;
            #pragma unroll
            for(int i=0;i<16;i++)
                base[SWZA(mb+i,wk)]=__float2bfloat16_rn((float)((rW>>(sh+i))&1u));
        } else {
            #pragma unroll
            for(int i=0;i<16;i++){
                float v=0.f;
                if((rW>>(akq+i))&1u){
                    int mI=kk+akq+i;
                    v=(rqv+kt[mI]>0.f)?(q1v*kt[p.K1+mI]):(q2v*kt[2*p.K1+mI]);
                }
                __nv_bfloat16 h=__float2bfloat16_rn(v);
                int o=SWZA(ar,akq+i);
                base[o]=h; base[OFF_AL+o]=__float2bfloat16_rn(v-__bfloat162float(h));
            }
        }
        {
            __nv_bfloat162 hp[4], lp[4];
            #pragma unroll
            for(int j=0;j<4;j++){
                float x0=rB[2*j], x1=rB[2*j+1];
                __nv_bfloat16 h0=__float2bfloat16_rn(x0), h1=__float2bfloat16_rn(x1);
                hp[j]=__nv_bfloat162(h0,h1);
                lp[j]=__nv_bfloat162(__float2bfloat16_rn(x0-__bfloat162float(h0)),
                                     __float2bfloat16_rn(x1-__bfloat162float(h1)));
            }
            int o=SWZB(br,bnq);
            *(uint4*)(base+OFF_BH+o)=*(uint4*)hp;
            *(uint4*)(base+OFF_BL+o)=*(uint4*)lp;
        }
    };

    loadregs(0);
    for(int it=0;it<niter;it++){
        int buf=it&1;
        storesm(buf,it<<5);
        __syncthreads();
        if(it+1<niter) loadregs(it+1);
        unsigned bo=(unsigned)buf*SSTR*2u;
        #pragma unroll
        for(int k2=0;k2<2;k2++){
            unsigned aH[2][4], aL[2][4], bH[2][4], bL[2][4];
            #pragma unroll
            for(int mt=0;mt<2;mt++){
                LDSM4(aH[mt], aAddr[mt][k2]+bo);
                if(ASRC!=1) LDSM4(aL[mt], aAddr[mt][k2]+bo+2u*OFF_AL);
            }
            #pragma unroll
            for(int pp=0;pp<2;pp++){
                LDSM4T(bH[pp], bAddr[pp][k2]+bo);
                LDSM4T(bL[pp], bAddr[pp][k2]+bo+2u*(OFF_BL-OFF_BH));
            }
            #pragma unroll
            for(int mt=0;mt<2;mt++)
                #pragma unroll
                for(int nt=0;nt<4;nt++){
                    const unsigned* bh=&bH[nt>>1][(nt&1)*2];
                    const unsigned* bl=&bL[nt>>1][(nt&1)*2];
                    mma16816(acc[mt][nt],aH[mt],bh);
                    mma16816(acc[mt][nt],aH[mt],bl);
                    if(ASRC!=1) mma16816(acc[mt][nt],aL[mt],bh);
                }
        }
        __syncthreads();
    }
    #pragma unroll
    for(int mt=0;mt<2;mt++)
        #pragma unroll
        for(int nt=0;nt<4;nt++){
            long long r0=m0+wm*32+mt*16+g;
            int col=n0+wn*32+nt*8+tc*2;
            float* cp0=C+r0*p.ldc+col; float* cp1=C+(r0+8)*p.ldc+col;
            const float *e10=nullptr,*e20=nullptr,*e11=nullptr,*e21=nullptr;
            if(EPI==1){
                e10=p.E1+r0*p.ldc+col; e20=p.E2+r0*p.ldc+col;
                e11=p.E1+(r0+8)*p.ldc+col; e21=p.E2+(r0+8)*p.ldc+col;
            }
            epi_pair<EPI>(acc[mt][nt][0],acc[mt][nt][1],cp0,e10,e20);
            epi_pair<EPI>(acc[mt][nt][2],acc[mt][nt][3],cp1,e11,e21);
        }
}

static void gemm_go(int asrc,int epi,const GP& p,int zc){
    dim3 g(p.M/128,p.N/64,zc);
    if(asrc==1)      gemm_k<1,0><<<g,256,SMB>>>(p);
    else if(asrc==2) gemm_k<2,2><<<g,256,SMB>>>(p);
    else if(epi==0)  gemm_k<0,0><<<g,256,SMB>>>(p);
    else if(epi==1)  gemm_k<0,1><<<g,256,SMB>>>(p);
    else             gemm_k<0,2><<<g,256,SMB>>>(p);
}
static void proj_go(const float* X,int rows,const float* Wt,float* out){
    GP p{}; p.M=rows; p.N=512; p.K1=512; p.Hdiv=1;
    p.A1=X; p.lda1=512; p.B1=Wt; p.ldb1=512; p.C=out; p.ldc=512;
    gemm_go(0,0,p,1);
}
static void fusion_go(const float* a,const float* bm,int rows,const float* W,const float* U,
                      const float* Wf,const float* Uf,float* P1,float* out){
    GP p{}; p.M=rows; p.N=512; p.K1=512; p.K2=512; p.Hdiv=1;
    p.A1=a; p.lda1=512; p.B1=W; p.ldb1=512;
    p.A2=bm; p.lda2=512; p.B2=U; p.ldb2=512;
    p.C=P1; p.ldc=512;
    gemm_go(0,0,p,1);
    p.B1=Wf; p.B2=Uf; p.C=out; p.E1=P1; p.E2=a;
    gemm_go(0,1,p,1);
}
static void attn_go(float* S,const float* q,int Nqq,const float* kv,int Nkv,
                    const float* Wt,const float* a1,const float* a2,
                    const unsigned* bits,int bld,long long sb,float* agg){
    float *projQ=S+O_PJQ,*projK=S+O_PJK;
    float *rq=S+O_EQ,*rk=S+O_EK,*q1=S+O_Q1,*k1=S+O_K1,*q2=S+O_Q2,*k2=S+O_K2;
    float *cs=S+O_CSC,*ps=S+O_PS;
    proj_go(q,NB*Nqq,Wt,projQ);
    proj_go(kv,NB*Nkv,Wt,projK);
    dot_a_k<<<(NB*HH*Nqq+255)/256,256>>>(projQ,a1,rq,q1,q2,Nqq);
    dot_a_k<<<(NB*HH*Nkv+255)/256,256>>>(projK,a2,rk,k1,k2,Nkv);
    int nch=Nqq/256;
    bitsum_k<<<dim3(Nkv/128,nch,NB),128>>>(bits,rq,q1,q2,rk,k1,k2,ps,Nqq,Nkv,bld,nch,sb);
    csmerge_k<<<(NB*HH*Nkv+255)/256,256>>>(ps,cs,Nkv,nch);
    GP p{}; p.M=Nqq; p.N=64; p.K1=Nkv; p.Hdiv=HH;
    p.B1=projK; p.ldb1=512; p.sB_b=(long long)Nkv*512; p.sB_h=64;
    p.C=agg; p.ldc=512; p.sC_b=(long long)Nqq*512; p.sC_h=64;
    p.scv=cs; p.sSc=Nkv;
    p.qr=rq; p.qe1=q1; p.qe2=q2; p.kr=rk; p.ke1=k1; p.ke2=k2;
    p.bits=bits; p.bld=bld; p.sBits_b=sb;
    gemm_go(2,2,p,NB*HH);
}

extern "C" void kernel_launch(void* const* d_in, const int* in_sizes, int n_in,
                              void* d_out, int out_size){
    cudaFuncSetAttribute(gemm_k<0,0>,cudaFuncAttributeMaxDynamicSharedMemorySize,SMB);
    cudaFuncSetAttribute(gemm_k<0,1>,cudaFuncAttributeMaxDynamicSharedMemorySize,SMB);
    cudaFuncSetAttribute(gemm_k<2,2>,cudaFuncAttributeMaxDynamicSharedMemorySize,SMB);
    cudaFuncSetAttribute(gemm_k<1,0>,cudaFuncAttributeMaxDynamicSharedMemorySize,SMB);
    float* S; cudaGetSymbolAddress((void**)&S, d_scratch);
    const float* in_g=(const float*)d_in[0];
    const float* in_c=(const float*)d_in[1];
    const float* in_q=(const float*)d_in[2];
    const int* adj_gc=(const int*)d_in[3];
    const int* adj_gq=(const int*)d_in[4];
    const float* aW[3]={(const float*)d_in[5],(const float*)d_in[8],(const float*)d_in[11]};
    const float* aa1[3]={(const float*)d_in[6],(const float*)d_in[9],(const float*)d_in[12]};
    const float* aa2[3]={(const float*)d_in[7],(const float*)d_in[10],(const float*)d_in[13]};
    const float* fW=(const float*)d_in[14];
    const float* fU=(const float*)d_in[15];
    const float* fWf=(const float*)d_in[16];
    const float* fUf=(const float*)d_in[17];
    float* out=(float*)d_out;

    unsigned* bgc=(unsigned*)(S+O_BGC);
    unsigned* bgq=(unsigned*)(S+O_BGQ);
    unsigned* bgqT=(unsigned*)(S+O_BGQT);
    float* Wt=S+O_WT;
    float *gsame=S+O_GS, *agg=S+O_AGG, *P1=S+O_P1, *G1tmp=S+O_G1;

    bitpack_k<<<512,256>>>(adj_gc,bgc,131072);
    bitpack_k<<<128,256>>>(adj_gq,bgq,32768);
    bitpackT_k<<<128,256>>>(adj_gq,bgqT);
    repack3_k<<<(3*2*HH*FF*DD+255)/256,256>>>(aW[0],aW[1],aW[2],Wt);

    for(int l=0;l<2;l++){
        const float *Gin,*Cin,*Qin; float *Gout,*Cout,*Qout;
        if(l==0){ Gin=in_g; Cin=in_c; Qin=in_q; Gout=S+O_G0; Cout=S+O_C0; Qout=S+O_Q0; }
        else    { Gin=S+O_G0; Cin=S+O_C0; Qin=S+O_Q0;
                  Gout=out; Cout=out+SZ_GF; Qout=out+2*SZ_GF; }
        const float* fWl=fW+(size_t)l*4*FF*FF;  const float* fUl=fU+(size_t)l*4*FF*FF;
        const float* fWfl=fWf+(size_t)l*4*FF*FF; const float* fUfl=fUf+(size_t)l*4*FF*FF;
        {
            GP p{}; p.M=NC; p.N=512; p.K1=NG; p.Hdiv=1;
            p.bits=bgc; p.bld=NC/32; p.sBits_b=(long long)NG*(NC/32);
            p.B1=Gin; p.ldb1=512; p.sB_b=(long long)NG*512;
            p.C=gsame; p.ldc=512; p.sC_b=(long long)NC*512;
            gemm_go(1,0,p,NB);
        }
        fusion_go(Cin,gsame,NB*NC, fWl+0*FF*FF,fUl+0*FF*FF,fWfl+0*FF*FF,fUfl+0*FF*FF, P1,Cout);
        attn_go(S,Gin,NG,Cin,NC, Wt+(size_t)(0*2+l)*FF*512, aa1[0]+l*HH*DD, aa2[0]+l*HH*DD,
                bgc,NC/32,(long long)NG*(NC/32), agg);
        fusion_go(Gin,agg,NB*NG, fWl+1*FF*FF,fUl+1*FF*FF,fWfl+1*FF*FF,fUfl+1*FF*FF, P1,G1tmp);
        attn_go(S,Qin,NQ,Gin,NG, Wt+(size_t)(1*2+l)*FF*512, aa1[1]+l*HH*DD, aa2[1]+l*HH*DD,
                bgqT,NG/32,(long long)NQ*(NG/32), agg);
        fusion_go(Qin,agg,NB*NQ, fWl+2*FF*FF,fUl+2*FF*FF,fWfl+2*FF*FF,fUfl+2*FF*FF, P1,Qout);
        attn_go(S,Gin,NG,Qin,NQ, Wt+(size_t)(2*2+l)*FF*512, aa1[2]+l*HH*DD, aa2[2]+l*HH*DD,
                bgq,NQ/32,(long long)NG*(NQ/32), agg);
        fusion_go(G1tmp,agg,NB*NG, fWl+3*FF*FF,fUl+3*FF*FF,fWfl+3*FF*FF,fUfl+3*FF*FF, P1,Gout);
    }
}